// round 1
// baseline (speedup 1.0000x reference)
#include <cuda_runtime.h>
#include <math.h>

#define HID     1024
#define BATCH   32
#define NLAYERS 3
#define NOUT    2500
#define NG      50
#define MODES   32
#define GATES   (3*HID)
#define KC      128

// Persistent scratch (no allocations allowed)
__device__ float g_h[2][NLAYERS][BATCH][HID];  // ping-pong hidden state
__device__ float g_x[BATCH][HID];              // spectrally-cropped input for next step
__device__ float g_ct[NG];                     // cos(2*pi*i/50)
__device__ float g_st[NG];                     // sin(2*pi*i/50)

// -------------------------------------------------------------------------
// Init: zero hidden state, build trig tables. Runs every launch (deterministic).
// -------------------------------------------------------------------------
__global__ void init_kernel() {
    int tid = blockIdx.x * blockDim.x + threadIdx.x;
    int total = 2 * NLAYERS * BATCH * HID;
    float* h = (float*)g_h;
    for (int i = tid; i < total; i += gridDim.x * blockDim.x) h[i] = 0.0f;
    if (tid < NG) {
        float ang = (2.0f * 3.14159265358979323846f * (float)tid) / (float)NG;
        g_ct[tid] = cosf(ang);
        g_st[tid] = sinf(ang);
    }
}

// -------------------------------------------------------------------------
// One GRU layer: hnew[b][j] for all b (lanes) and j (warps across grid).
// lane = batch. Warp-uniform float4 weight loads (L2), x/h transposed in SMEM.
// -------------------------------------------------------------------------
__global__ __launch_bounds__(256, 1) void gru_kernel(
    const float* __restrict__ inp,    // [BATCH][HID]
    const float* __restrict__ hprev,  // [BATCH][HID]
    float*       __restrict__ hnew,   // [BATCH][HID]
    const float* __restrict__ Wih,    // [3*HID][HID]
    const float* __restrict__ Whh,    // [3*HID][HID]
    const float* __restrict__ bih,    // [3*HID]
    const float* __restrict__ bhh)    // [3*HID]
{
    __shared__ float Xs[KC][BATCH + 1];
    __shared__ float Hs[KC][BATCH + 1];

    const int tid  = threadIdx.x;
    const int warp = tid >> 5;
    const int lane = tid & 31;
    const int j    = warp * gridDim.x + blockIdx.x;   // hidden-unit index
    const bool active = (j < HID);
    const int jc = active ? j : (HID - 1);

    const float4* wri = (const float4*)(Wih + (size_t)(0 * HID + jc) * HID);
    const float4* wzi = (const float4*)(Wih + (size_t)(1 * HID + jc) * HID);
    const float4* wni = (const float4*)(Wih + (size_t)(2 * HID + jc) * HID);
    const float4* wrh = (const float4*)(Whh + (size_t)(0 * HID + jc) * HID);
    const float4* wzh = (const float4*)(Whh + (size_t)(1 * HID + jc) * HID);
    const float4* wnh = (const float4*)(Whh + (size_t)(2 * HID + jc) * HID);

    float air = 0.f, aiz = 0.f, ain = 0.f;
    float ahr = 0.f, ahz = 0.f, ahn = 0.f;

    for (int kb = 0; kb < HID; kb += KC) {
        // cooperative transposed load of x/h chunk
        for (int i = tid; i < KC * BATCH; i += 256) {
            int b = i >> 7;          // i / KC  (KC == 128)
            int k = i & (KC - 1);
            Xs[k][b] = inp[b * HID + kb + k];
            Hs[k][b] = hprev[b * HID + kb + k];
        }
        __syncthreads();

        if (active) {
            const int k4b = kb >> 2;
            #pragma unroll 4
            for (int k4 = 0; k4 < KC / 4; ++k4) {
                float4 vir = wri[k4b + k4];
                float4 viz = wzi[k4b + k4];
                float4 vin = wni[k4b + k4];
                float4 vhr = wrh[k4b + k4];
                float4 vhz = wzh[k4b + k4];
                float4 vhn = wnh[k4b + k4];
                int k = k4 << 2;
                float xv, hv;
                xv = Xs[k + 0][lane]; hv = Hs[k + 0][lane];
                air += vir.x * xv; aiz += viz.x * xv; ain += vin.x * xv;
                ahr += vhr.x * hv; ahz += vhz.x * hv; ahn += vhn.x * hv;
                xv = Xs[k + 1][lane]; hv = Hs[k + 1][lane];
                air += vir.y * xv; aiz += viz.y * xv; ain += vin.y * xv;
                ahr += vhr.y * hv; ahz += vhz.y * hv; ahn += vhn.y * hv;
                xv = Xs[k + 2][lane]; hv = Hs[k + 2][lane];
                air += vir.z * xv; aiz += viz.z * xv; ain += vin.z * xv;
                ahr += vhr.z * hv; ahz += vhz.z * hv; ahn += vhn.z * hv;
                xv = Xs[k + 3][lane]; hv = Hs[k + 3][lane];
                air += vir.w * xv; aiz += viz.w * xv; ain += vin.w * xv;
                ahr += vhr.w * hv; ahz += vhz.w * hv; ahn += vhn.w * hv;
            }
        }
        __syncthreads();
    }

    if (active) {
        float ir  = air + bih[j];
        float iz  = aiz + bih[HID + j];
        float inn = ain + bih[2 * HID + j];
        float hr  = ahr + bhh[j];
        float hz  = ahz + bhh[HID + j];
        float hn  = ahn + bhh[2 * HID + j];
        float r = 1.0f / (1.0f + __expf(-(ir + hr)));
        float z = 1.0f / (1.0f + __expf(-(iz + hz)));
        float n = tanhf(inn + r * hn);
        float hp = hprev[lane * HID + j];
        hnew[lane * HID + j] = (1.0f - z) * n + z * hp;
    }
}

// -------------------------------------------------------------------------
// FC: out[b][n] = h[b] . fc_w[n] + fc_b[n].  Warp per n, lane = batch.
// -------------------------------------------------------------------------
__global__ __launch_bounds__(256, 1) void fc_kernel(
    const float* __restrict__ h,    // [BATCH][HID]
    const float* __restrict__ fcw,  // [NOUT][HID]
    const float* __restrict__ fcb,  // [NOUT]
    float*       __restrict__ out)  // [BATCH][NOUT] slice of d_out
{
    __shared__ float Hs[KC][BATCH + 1];
    const int tid  = threadIdx.x;
    const int warp = tid >> 5;
    const int lane = tid & 31;
    const int n  = blockIdx.x * 8 + warp;
    const int nc = (n < NOUT) ? n : (NOUT - 1);
    const float4* w = (const float4*)(fcw + (size_t)nc * HID);

    float acc = 0.f;
    for (int kb = 0; kb < HID; kb += KC) {
        for (int i = tid; i < KC * BATCH; i += 256) {
            int b = i >> 7;
            int k = i & (KC - 1);
            Hs[k][b] = h[b * HID + kb + k];
        }
        __syncthreads();
        const int k4b = kb >> 2;
        #pragma unroll 4
        for (int k4 = 0; k4 < KC / 4; ++k4) {
            float4 v = w[k4b + k4];
            int k = k4 << 2;
            acc += v.x * Hs[k + 0][lane];
            acc += v.y * Hs[k + 1][lane];
            acc += v.z * Hs[k + 2][lane];
            acc += v.w * Hs[k + 3][lane];
        }
        __syncthreads();
    }
    if (n < NOUT) out[lane * NOUT + n] = acc + fcb[n];
}

// -------------------------------------------------------------------------
// Spectral crop: x_next[b][m1*32+m2] = Re F[k1][k2], k=(m+34)%50, via
// separable cos/sin contractions. One block per batch.
// -------------------------------------------------------------------------
__global__ __launch_bounds__(256, 1) void spectral_kernel(
    const float* __restrict__ out)   // [BATCH][NOUT] slice just written
{
    __shared__ float sq[NG * NG];        // 2500
    __shared__ float Pc[NG][MODES];      // 50 x 32
    __shared__ float Ps[NG][MODES];
    __shared__ float ct[NG], st[NG];

    const int b = blockIdx.x;
    const int tid = threadIdx.x;
    const float* o = out + (size_t)b * NOUT;

    for (int i = tid; i < NOUT; i += 256) sq[i] = o[i];
    if (tid < NG) { ct[tid] = g_ct[tid]; st[tid] = g_st[tid]; }
    __syncthreads();

    // Stage A: contract n2.  Pc[n1][m2] = sum_n2 sq[n1][n2]*cos(2pi*k2*n2/50)
    for (int i = tid; i < NG * MODES; i += 256) {
        int n1 = i / MODES, m2 = i % MODES;
        int k2 = (m2 + 34) % NG;
        float sc = 0.f, ss = 0.f;
        int idx = 0;
        #pragma unroll 1
        for (int n2 = 0; n2 < NG; ++n2) {
            float v = sq[n1 * NG + n2];
            sc += v * ct[idx];
            ss += v * st[idx];
            idx += k2; if (idx >= NG) idx -= NG;
        }
        Pc[n1][m2] = sc;
        Ps[n1][m2] = ss;
    }
    __syncthreads();

    // Stage B: contract n1 with cos(a+b) = ca*cb - sa*sb
    for (int i = tid; i < MODES * MODES; i += 256) {
        int m1 = i / MODES, m2 = i % MODES;
        int k1 = (m1 + 34) % NG;
        float acc = 0.f;
        int idx = 0;
        #pragma unroll 1
        for (int n1 = 0; n1 < NG; ++n1) {
            acc += ct[idx] * Pc[n1][m2] - st[idx] * Ps[n1][m2];
            idx += k1; if (idx >= NG) idx -= NG;
        }
        g_x[b][i] = acc;
    }
}

// -------------------------------------------------------------------------
// Launch: 1 init + T * (3 GRU + FC + spectral) kernel nodes, graph-capturable.
// -------------------------------------------------------------------------
extern "C" void kernel_launch(void* const* d_in, const int* in_sizes, int n_in,
                              void* d_out, int out_size) {
    const float* x   = (const float*)d_in[0];
    const float* Wih = (const float*)d_in[1];
    const float* Whh = (const float*)d_in[2];
    const float* bih = (const float*)d_in[3];
    const float* bhh = (const float*)d_in[4];
    const float* fcw = (const float*)d_in[5];
    const float* fcb = (const float*)d_in[6];
    float* out = (float*)d_out;

    const int T = out_size / (BATCH * NOUT);  // time_size (device scalar unreadable under capture)

    float* hbase; cudaGetSymbolAddress((void**)&hbase, g_h);
    float* xbase; cudaGetSymbolAddress((void**)&xbase, g_x);

    init_kernel<<<96, 256>>>();

    for (int t = 0; t < T; ++t) {
        const int p = t & 1, c = p ^ 1;
        const float* inp = (t == 0) ? x : xbase;
        for (int l = 0; l < NLAYERS; ++l) {
            const float* hp = hbase + ((size_t)p * NLAYERS + l) * BATCH * HID;
            float*       hc = hbase + ((size_t)c * NLAYERS + l) * BATCH * HID;
            gru_kernel<<<148, 256>>>(inp, hp, hc,
                                     Wih + (size_t)l * GATES * HID,
                                     Whh + (size_t)l * GATES * HID,
                                     bih + l * GATES,
                                     bhh + l * GATES);
            inp = hc;
        }
        float* oslice = out + (size_t)t * BATCH * NOUT;
        fc_kernel<<<(NOUT + 7) / 8, 256>>>(
            hbase + ((size_t)c * NLAYERS + (NLAYERS - 1)) * BATCH * HID, fcw, fcb, oslice);
        spectral_kernel<<<BATCH, 256>>>(oslice);
    }
}

// round 3
// speedup vs baseline: 1.8188x; 1.8188x over previous
#include <cuda_runtime.h>
#include <math.h>

#define HID     1024
#define BATCH   32
#define NLAYERS 3
#define NOUT    2500
#define NG      50
#define MODES   32
#define GATES   (3*HID)
#define KC      64
#define NCHUNK  (HID/KC)     // 16
#define JB      4            // hidden units per block (1 per warp)
#define FC_NB   16           // fc outputs per block (4 per warp)

// Persistent scratch (transposed [feature][batch] layouts)
__device__ float g_h[2][NLAYERS][HID][BATCH];
__device__ float g_x[HID * BATCH];       // [j][b] spectrally-cropped input
__device__ float g_ct[NG];
__device__ float g_st[NG];

// ---------------- cp.async helpers ----------------
__device__ __forceinline__ void cp16(void* dst, const void* src) {
    unsigned d = (unsigned)__cvta_generic_to_shared(dst);
    asm volatile("cp.async.cg.shared.global [%0], [%1], 16;\n" :: "r"(d), "l"(src));
}
__device__ __forceinline__ void cp_commit() { asm volatile("cp.async.commit_group;\n"); }
template<int N> __device__ __forceinline__ void cp_wait() {
    asm volatile("cp.async.wait_group %0;\n" :: "n"(N));
}

// ---------------- init: zero h, trig tables, transpose x0 ----------------
__global__ void init_kernel(const float* __restrict__ x) {
    int tid = blockIdx.x * blockDim.x + threadIdx.x;
    int stride = gridDim.x * blockDim.x;
    float* h = (float*)g_h;
    int total = 2 * NLAYERS * HID * BATCH;
    for (int i = tid; i < total; i += stride) h[i] = 0.0f;
    for (int i = tid; i < HID * BATCH; i += stride) {
        int j = i >> 5, b = i & 31;
        g_x[i] = x[b * HID + j];           // transpose [b][j] -> [j][b]
    }
    if (tid < NG) {
        float ang = 6.283185307179586f * (float)tid / (float)NG;
        g_ct[tid] = cosf(ang);
        g_st[tid] = sinf(ang);
    }
}

// ---------------- GRU layer ----------------
// block: 128 threads = 4 warps, warp w owns hidden unit j = blockIdx.x*4 + w,
// lane = batch. Weights + x/h chunks staged via cp.async, double-buffered.
__global__ __launch_bounds__(128) void gru_kernel(
    const float* __restrict__ xT,     // [HID][BATCH] layer input (transposed)
    const float* __restrict__ hT,     // [HID][BATCH] prev hidden (transposed)
    float*       __restrict__ hnT,    // [HID][BATCH] new hidden
    const float* __restrict__ Wih,    // [3*HID][HID]
    const float* __restrict__ Whh,    // [3*HID][HID]
    const float* __restrict__ bih,
    const float* __restrict__ bhh)
{
    __shared__ __align__(16) float Ws[2][JB * 6][KC];     // 12 KB
    __shared__ __align__(16) float Xs[2][KC][BATCH];      // 16 KB
    __shared__ __align__(16) float Hs[2][KC][BATCH];      // 16 KB

    const int tid  = threadIdx.x;
    const int warp = tid >> 5;
    const int lane = tid & 31;
    const int j0   = blockIdx.x * JB;

    // one chunk = 384 (weights) + 512 (X) + 512 (H) 16B copies = 11 per thread
    auto load_chunk = [&](int c, int buf) {
        const int kb = c * KC;
        #pragma unroll
        for (int it = 0; it < 11; ++it) {
            int i = tid + it * 128;
            if (i < 384) {
                int jg = i >> 4, off = i & 15;      // 24 rows x 16 segs
                int jl = jg / 6, g = jg % 6;
                const float* base = (g < 3)
                    ? Wih + ((size_t)g * HID + j0 + jl) * HID
                    : Whh + ((size_t)(g - 3) * HID + j0 + jl) * HID;
                cp16(&Ws[buf][jg][off * 4], base + kb + off * 4);
            } else if (i < 896) {
                int r = i - 384; int k = r >> 3, off = r & 7;
                cp16(&Xs[buf][k][off * 4], xT + (size_t)(kb + k) * BATCH + off * 4);
            } else {
                int r = i - 896; int k = r >> 3, off = r & 7;
                cp16(&Hs[buf][k][off * 4], hT + (size_t)(kb + k) * BATCH + off * 4);
            }
        }
        cp_commit();
    };

    float a0 = 0.f, a1 = 0.f, a2 = 0.f, a3 = 0.f, a4 = 0.f, a5 = 0.f;

    load_chunk(0, 0);
    for (int c = 0; c < NCHUNK; ++c) {
        const int buf = c & 1;
        if (c + 1 < NCHUNK) { load_chunk(c + 1, buf ^ 1); cp_wait<1>(); }
        else                { cp_wait<0>(); }
        __syncthreads();

        #pragma unroll
        for (int k4 = 0; k4 < KC / 4; ++k4) {
            float4 w0 = *(const float4*)&Ws[buf][warp * 6 + 0][k4 * 4];
            float4 w1 = *(const float4*)&Ws[buf][warp * 6 + 1][k4 * 4];
            float4 w2 = *(const float4*)&Ws[buf][warp * 6 + 2][k4 * 4];
            float4 w3 = *(const float4*)&Ws[buf][warp * 6 + 3][k4 * 4];
            float4 w4 = *(const float4*)&Ws[buf][warp * 6 + 4][k4 * 4];
            float4 w5 = *(const float4*)&Ws[buf][warp * 6 + 5][k4 * 4];
            float xv, hv;
            xv = Xs[buf][k4 * 4 + 0][lane]; hv = Hs[buf][k4 * 4 + 0][lane];
            a0 += w0.x * xv; a1 += w1.x * xv; a2 += w2.x * xv;
            a3 += w3.x * hv; a4 += w4.x * hv; a5 += w5.x * hv;
            xv = Xs[buf][k4 * 4 + 1][lane]; hv = Hs[buf][k4 * 4 + 1][lane];
            a0 += w0.y * xv; a1 += w1.y * xv; a2 += w2.y * xv;
            a3 += w3.y * hv; a4 += w4.y * hv; a5 += w5.y * hv;
            xv = Xs[buf][k4 * 4 + 2][lane]; hv = Hs[buf][k4 * 4 + 2][lane];
            a0 += w0.z * xv; a1 += w1.z * xv; a2 += w2.z * xv;
            a3 += w3.z * hv; a4 += w4.z * hv; a5 += w5.z * hv;
            xv = Xs[buf][k4 * 4 + 3][lane]; hv = Hs[buf][k4 * 4 + 3][lane];
            a0 += w0.w * xv; a1 += w1.w * xv; a2 += w2.w * xv;
            a3 += w3.w * hv; a4 += w4.w * hv; a5 += w5.w * hv;
        }
        __syncthreads();
    }

    const int j = j0 + warp;
    float ir  = a0 + bih[j];
    float iz  = a1 + bih[HID + j];
    float inn = a2 + bih[2 * HID + j];
    float hr  = a3 + bhh[j];
    float hz  = a4 + bhh[HID + j];
    float hn  = a5 + bhh[2 * HID + j];
    float r = 1.0f / (1.0f + __expf(-(ir + hr)));
    float z = 1.0f / (1.0f + __expf(-(iz + hz)));
    float n = tanhf(inn + r * hn);
    float hp = hT[(size_t)j * BATCH + lane];
    hnT[(size_t)j * BATCH + lane] = (1.0f - z) * n + z * hp;
}

// ---------------- FC ----------------
// block: 128 threads = 4 warps, warp owns 4 outputs, lane = batch.
__global__ __launch_bounds__(128) void fc_kernel(
    const float* __restrict__ hT,    // [HID][BATCH]
    const float* __restrict__ fcw,   // [NOUT][HID]
    const float* __restrict__ fcb,
    float*       __restrict__ out)   // [BATCH][NOUT] slice
{
    __shared__ __align__(16) float Ws[2][FC_NB][KC];     // 8 KB
    __shared__ __align__(16) float Hs[2][KC][BATCH];     // 16 KB

    const int tid  = threadIdx.x;
    const int warp = tid >> 5;
    const int lane = tid & 31;
    const int n0   = blockIdx.x * FC_NB;

    // 256 (weights) + 512 (H) copies = 6 per thread
    auto load_chunk = [&](int c, int buf) {
        const int kb = c * KC;
        #pragma unroll
        for (int it = 0; it < 6; ++it) {
            int i = tid + it * 128;
            if (i < 256) {
                int row = i >> 4, off = i & 15;
                int n = n0 + row; if (n > NOUT - 1) n = NOUT - 1;
                cp16(&Ws[buf][row][off * 4], fcw + (size_t)n * HID + kb + off * 4);
            } else {
                int r = i - 256; int k = r >> 3, off = r & 7;
                cp16(&Hs[buf][k][off * 4], hT + (size_t)(kb + k) * BATCH + off * 4);
            }
        }
        cp_commit();
    };

    float a0 = 0.f, a1 = 0.f, a2 = 0.f, a3 = 0.f;

    load_chunk(0, 0);
    for (int c = 0; c < NCHUNK; ++c) {
        const int buf = c & 1;
        if (c + 1 < NCHUNK) { load_chunk(c + 1, buf ^ 1); cp_wait<1>(); }
        else                { cp_wait<0>(); }
        __syncthreads();

        #pragma unroll
        for (int k4 = 0; k4 < KC / 4; ++k4) {
            float4 w0 = *(const float4*)&Ws[buf][warp * 4 + 0][k4 * 4];
            float4 w1 = *(const float4*)&Ws[buf][warp * 4 + 1][k4 * 4];
            float4 w2 = *(const float4*)&Ws[buf][warp * 4 + 2][k4 * 4];
            float4 w3 = *(const float4*)&Ws[buf][warp * 4 + 3][k4 * 4];
            float hv;
            hv = Hs[buf][k4 * 4 + 0][lane];
            a0 += w0.x * hv; a1 += w1.x * hv; a2 += w2.x * hv; a3 += w3.x * hv;
            hv = Hs[buf][k4 * 4 + 1][lane];
            a0 += w0.y * hv; a1 += w1.y * hv; a2 += w2.y * hv; a3 += w3.y * hv;
            hv = Hs[buf][k4 * 4 + 2][lane];
            a0 += w0.z * hv; a1 += w1.z * hv; a2 += w2.z * hv; a3 += w3.z * hv;
            hv = Hs[buf][k4 * 4 + 3][lane];
            a0 += w0.w * hv; a1 += w1.w * hv; a2 += w2.w * hv; a3 += w3.w * hv;
        }
        __syncthreads();
    }

    const int n = n0 + warp * 4;
    if (n + 0 < NOUT) out[(size_t)lane * NOUT + n + 0] = a0 + fcb[n + 0];
    if (n + 1 < NOUT) out[(size_t)lane * NOUT + n + 1] = a1 + fcb[n + 1];
    if (n + 2 < NOUT) out[(size_t)lane * NOUT + n + 2] = a2 + fcb[n + 2];
    if (n + 3 < NOUT) out[(size_t)lane * NOUT + n + 3] = a3 + fcb[n + 3];
}

// ---------------- spectral crop ----------------
__global__ __launch_bounds__(256) void spectral_kernel(
    const float* __restrict__ out)   // [BATCH][NOUT] slice just written
{
    __shared__ float sq[NG * NG];
    __shared__ float Pc[NG][MODES];
    __shared__ float Ps[NG][MODES];
    __shared__ float ct[NG], st[NG];

    const int b = blockIdx.x;
    const int tid = threadIdx.x;
    const float* o = out + (size_t)b * NOUT;

    for (int i = tid; i < NOUT; i += 256) sq[i] = o[i];
    if (tid < NG) { ct[tid] = g_ct[tid]; st[tid] = g_st[tid]; }
    __syncthreads();

    for (int i = tid; i < NG * MODES; i += 256) {
        int n1 = i / MODES, m2 = i % MODES;
        int k2 = (m2 + 34) % NG;
        float sc = 0.f, ss = 0.f;
        int idx = 0;
        #pragma unroll 1
        for (int n2 = 0; n2 < NG; ++n2) {
            float v = sq[n1 * NG + n2];
            sc += v * ct[idx];
            ss += v * st[idx];
            idx += k2; if (idx >= NG) idx -= NG;
        }
        Pc[n1][m2] = sc;
        Ps[n1][m2] = ss;
    }
    __syncthreads();

    for (int i = tid; i < MODES * MODES; i += 256) {
        int m1 = i / MODES, m2 = i % MODES;
        int k1 = (m1 + 34) % NG;
        float acc = 0.f;
        int idx = 0;
        #pragma unroll 1
        for (int n1 = 0; n1 < NG; ++n1) {
            acc += ct[idx] * Pc[n1][m2] - st[idx] * Ps[n1][m2];
            idx += k1; if (idx >= NG) idx -= NG;
        }
        g_x[i * BATCH + b] = acc;     // store transposed [j][b]
    }
}

// ---------------- driver ----------------
extern "C" void kernel_launch(void* const* d_in, const int* in_sizes, int n_in,
                              void* d_out, int out_size) {
    const float* x   = (const float*)d_in[0];
    const float* Wih = (const float*)d_in[1];
    const float* Whh = (const float*)d_in[2];
    const float* bih = (const float*)d_in[3];
    const float* bhh = (const float*)d_in[4];
    const float* fcw = (const float*)d_in[5];
    const float* fcb = (const float*)d_in[6];
    float* out = (float*)d_out;

    const int T = out_size / (BATCH * NOUT);

    float* hbase; cudaGetSymbolAddress((void**)&hbase, g_h);
    float* xbase; cudaGetSymbolAddress((void**)&xbase, g_x);

    init_kernel<<<96, 256>>>(x);

    for (int t = 0; t < T; ++t) {
        const int p = t & 1, c = p ^ 1;
        const float* inp = xbase;                 // [j][b]; init wrote t=0 input
        for (int l = 0; l < NLAYERS; ++l) {
            const float* hp = hbase + ((size_t)p * NLAYERS + l) * HID * BATCH;
            float*       hc = hbase + ((size_t)c * NLAYERS + l) * HID * BATCH;
            gru_kernel<<<HID / JB, 128>>>(inp, hp, hc,
                                          Wih + (size_t)l * GATES * HID,
                                          Whh + (size_t)l * GATES * HID,
                                          bih + l * GATES,
                                          bhh + l * GATES);
            inp = hc;
        }
        float* oslice = out + (size_t)t * BATCH * NOUT;
        fc_kernel<<<(NOUT + FC_NB - 1) / FC_NB, 128>>>(
            hbase + ((size_t)c * NLAYERS + (NLAYERS - 1)) * HID * BATCH, fcw, fcb, oslice);
        spectral_kernel<<<BATCH, 256>>>(oslice);
    }
}